// round 2
// baseline (speedup 1.0000x reference)
#include <cuda_runtime.h>

#define IMG   1024
#define OUTD  1016
#define TILE_H 32
#define TILE_W 128
#define IN_H  (TILE_H + 8)   // 40
#define IN_W  (TILE_W + 8)   // 136
#define MID_H (TILE_H + 4)   // 36
#define MID_W (TILE_W + 4)   // 132
#define NT    320

// out(i,j) = box5( (x_c - box5(x)/25) * (y_c - box5(y)/25) )(i,j) / 25
__global__ __launch_bounds__(NT) void cov_kernel(
    const float* __restrict__ x, const float* __restrict__ y,
    float* __restrict__ out)
{
    extern __shared__ float sm[];
    float* xs = sm;                      // IN_H * IN_W   raw tile
    float* hx = xs + IN_H * IN_W;        // IN_H * IN_W   horizontal 5-sums (reused for ht)
    float* Dv = hx + IN_H * IN_W;        // MID_H * MID_W dev product

    const int bx  = blockIdx.x * TILE_W;
    const int by  = blockIdx.y * TILE_H;
    const int n   = blockIdx.z;
    const int tid = threadIdx.x;

    const size_t ibase = (size_t)n * IMG * IMG;

    for (int img = 0; img < 2; ++img) {
        const float* src = (img == 0 ? x : y) + ibase;

        // ---- load IN_H x IN_W tile (float4, guarded at image edge) ----
        for (int w = tid; w < IN_H * (IN_W / 4); w += NT) {
            int r  = w / (IN_W / 4);
            int c4 = (w % (IN_W / 4)) * 4;
            int gr = by + r;
            int gc = bx + c4;
            float4 v;
            if (gr < IMG && gc + 3 < IMG) {
                v = *(const float4*)(src + (size_t)gr * IMG + gc);
            } else {
                v = make_float4(0.f, 0.f, 0.f, 0.f);
                if (gr < IMG) {
                    const float* row = src + (size_t)gr * IMG;
                    if (gc     < IMG) v.x = row[gc];
                    if (gc + 1 < IMG) v.y = row[gc + 1];
                    if (gc + 2 < IMG) v.z = row[gc + 2];
                    if (gc + 3 < IMG) v.w = row[gc + 3];
                }
            }
            *(float4*)(xs + r * IN_W + c4) = v;
        }
        __syncthreads();

        // ---- horizontal 5-sum: hx[r][c] = sum_{d<5} xs[r][c+d], rolling ----
        {
            const int NSEG = 8, SEGW = 17;                 // 8*17 >= MID_W(132)
            for (int w = tid; w < IN_H * NSEG; w += NT) {
                int r  = w / NSEG;
                int c0 = (w % NSEG) * SEGW;
                int c1 = min(c0 + SEGW, MID_W);
                const float* row = xs + r * IN_W;
                float s = row[c0] + row[c0+1] + row[c0+2] + row[c0+3] + row[c0+4];
                hx[r * IN_W + c0] = s;
                for (int c = c0 + 1; c < c1; ++c) {
                    s += row[c + 4] - row[c - 1];
                    hx[r * IN_W + c] = s;
                }
            }
        }
        __syncthreads();

        // ---- vertical 5-sum + deviation: Dv = (xdev) or Dv *= (ydev), rolling ----
        {
            const int NSEG = 2, SEGH = MID_H / NSEG;       // 18
            for (int w = tid; w < MID_W * NSEG; w += NT) {
                int q  = w / NSEG;
                int p0 = (w % NSEG) * SEGH;
                int p1 = p0 + SEGH;
                float s = hx[p0*IN_W + q] + hx[(p0+1)*IN_W + q] + hx[(p0+2)*IN_W + q]
                        + hx[(p0+3)*IN_W + q] + hx[(p0+4)*IN_W + q];
                for (int p = p0; p < p1; ++p) {
                    float dev = xs[(p + 2) * IN_W + q + 2] - s * 0.04f;
                    if (img == 0) Dv[p * MID_W + q]  = dev;
                    else          Dv[p * MID_W + q] *= dev;
                    if (p + 1 < p1) s += hx[(p + 5) * IN_W + q] - hx[p * IN_W + q];
                }
            }
        }
        __syncthreads();   // xs/hx are overwritten next image iteration
    }

    // ---- horizontal 5-sum of product into hx (as ht) ----
    {
        const int NSEG = 8, SEGW = TILE_W / NSEG;          // 16
        for (int w = tid; w < MID_H * NSEG; w += NT) {
            int p  = w / NSEG;
            int c0 = (w % NSEG) * SEGW;
            int c1 = c0 + SEGW;
            const float* row = Dv + p * MID_W;
            float s = row[c0] + row[c0+1] + row[c0+2] + row[c0+3] + row[c0+4];
            hx[p * IN_W + c0] = s;
            for (int c = c0 + 1; c < c1; ++c) {
                s += row[c + 4] - row[c - 1];
                hx[p * IN_W + c] = s;
            }
        }
    }
    __syncthreads();

    // ---- vertical 5-sum * 1/25 -> global store ----
    {
        const int NSEG = 2, SEGH = TILE_H / NSEG;          // 16
        float* ob = out + (size_t)n * OUTD * OUTD;
        for (int w = tid; w < TILE_W * NSEG; w += NT) {
            int j  = w / NSEG;
            int i0 = (w % NSEG) * SEGH;
            int i1 = i0 + SEGH;
            int ox = bx + j;
            if (ox >= OUTD) continue;
            float s = hx[i0*IN_W + j] + hx[(i0+1)*IN_W + j] + hx[(i0+2)*IN_W + j]
                    + hx[(i0+3)*IN_W + j] + hx[(i0+4)*IN_W + j];
            for (int i = i0; i < i1; ++i) {
                int oy = by + i;
                if (oy < OUTD) ob[(size_t)oy * OUTD + ox] = s * 0.04f;
                if (i + 1 < i1) s += hx[(i + 5) * IN_W + j] - hx[i * IN_W + j];
            }
        }
    }
}

extern "C" void kernel_launch(void* const* d_in, const int* in_sizes, int n_in,
                              void* d_out, int out_size) {
    const float* x = (const float*)d_in[0];
    const float* y = (const float*)d_in[1];
    // d_in[2] = mean_mask (uniform 1/25, folded into the 0.04f constants)
    float* out = (float*)d_out;

    const int smem = (2 * IN_H * IN_W + MID_H * MID_W) * (int)sizeof(float); // 62528 B
    cudaFuncSetAttribute(cov_kernel, cudaFuncAttributeMaxDynamicSharedMemorySize, smem);

    dim3 grid((OUTD + TILE_W - 1) / TILE_W,   // 8
              (OUTD + TILE_H - 1) / TILE_H,   // 32
              16);
    cov_kernel<<<grid, NT, smem>>>(x, y, out);
}

// round 3
// speedup vs baseline: 1.4521x; 1.4521x over previous
#include <cuda_runtime.h>

#define IMG    1024
#define OUTD   1016
#define TILE_W 128
#define TILE_H 48
#define IN_H   (TILE_H + 8)    // 56 input rows
#define MID_W  132             // horizontal-sum cols (outputs of 5-tap over 136)
#define MID_H  (TILE_H + 4)    // 52 deviation rows
#define HS     136             // smem row stride (floats), 544B = 34*16B
#define NT     320
#define NW     (NT / 32)       // 10 warps

__device__ __forceinline__ float4 ld4g(const float* __restrict__ img, int gr, int gc) {
    float4 v = make_float4(0.f, 0.f, 0.f, 0.f);
    if (gr < IMG) {
        const float* row = img + (size_t)gr * IMG;
        if (gc + 3 < IMG) {
            v = *(const float4*)(row + gc);
        } else {
            if (gc     < IMG) v.x = row[gc];
            if (gc + 1 < IMG) v.y = row[gc + 1];
            if (gc + 2 < IMG) v.z = row[gc + 2];
        }
    }
    return v;
}

// Warp-level horizontal 5-sum of one 136-float row held as: v = cols 4*ln..4*ln+3,
// v2 (lanes 0..1) = cols 128+4*ln..131+4*ln. Writes h[0..131] to hrow.
// If store_extra==false, only h[0..127] are written (enough for the product pass).
__device__ __forceinline__ void hrow_sum(float4 v, float4 v2, float* hrow, int ln,
                                         bool store_extra) {
    const unsigned m = 0xFFFFFFFFu;
    float4 n;
    n.x = __shfl_down_sync(m, v.x, 1);
    n.y = __shfl_down_sync(m, v.y, 1);
    n.z = __shfl_down_sync(m, v.z, 1);
    n.w = __shfl_down_sync(m, v.w, 1);
    float4 b0;
    b0.x = __shfl_sync(m, v2.x, 0);
    b0.y = __shfl_sync(m, v2.y, 0);
    b0.z = __shfl_sync(m, v2.z, 0);
    b0.w = __shfl_sync(m, v2.w, 0);
    if (ln == 31) n = b0;               // lane 31's right neighbor = cols 128..131

    float h0 = (v.x + v.y) + (v.z + v.w) + n.x;
    float h1 = h0 - v.x + n.y;
    float h2 = h1 - v.y + n.z;
    float h3 = h2 - v.z + n.w;
    *(float4*)(hrow + 4 * ln) = make_float4(h0, h1, h2, h3);

    if (store_extra) {
        float4 b1;
        b1.x = __shfl_sync(m, v2.x, 1);  // cols 132..135 (lane 1's v2)
        b1.y = __shfl_sync(m, v2.y, 1);
        b1.z = __shfl_sync(m, v2.z, 1);
        b1.w = __shfl_sync(m, v2.w, 1);
        if (ln == 0) {
            float g0 = (v2.x + v2.y) + (v2.z + v2.w) + b1.x;
            float g1 = g0 - v2.x + b1.y;
            float g2 = g1 - v2.y + b1.z;
            float g3 = g2 - v2.z + b1.w;
            *(float4*)(hrow + 128) = make_float4(g0, g1, g2, g3);
        }
    }
}

__global__ __launch_bounds__(NT, 3) void cov_kernel(
    const float* __restrict__ x, const float* __restrict__ y,
    float* __restrict__ out)
{
    extern __shared__ float sm[];
    float* hA = sm;              // [IN_H][HS]  : h-sums of x; later reused for prod
    float* hB = sm + IN_H * HS;  // [IN_H][HS]  : h-sums of y; later reused for hprod

    const int bx  = blockIdx.x * TILE_W;
    const int by  = blockIdx.y * TILE_H;
    const int n   = blockIdx.z;
    const int tid = threadIdx.x;
    const int wid = tid >> 5;
    const int ln  = tid & 31;

    const size_t ibase = (size_t)n * IMG * IMG;
    const float* xp = x + ibase;
    const float* yp = y + ibase;
    const float4 z4 = make_float4(0.f, 0.f, 0.f, 0.f);

    // ---- Phase 1: global load + warp-shuffle horizontal 5-sums for x and y ----
    for (int r = wid; r < IN_H; r += NW) {
        const int gr = by + r;
        float4 vx  = ld4g(xp, gr, bx + 4 * ln);
        float4 vx2 = (ln < 2) ? ld4g(xp, gr, bx + 128 + 4 * ln) : z4;
        hrow_sum(vx, vx2, hA + r * HS, ln, true);
        float4 vy  = ld4g(yp, gr, bx + 4 * ln);
        float4 vy2 = (ln < 2) ? ld4g(yp, gr, bx + 128 + 4 * ln) : z4;
        hrow_sum(vy, vy2, hB + r * HS, ln, true);
    }
    __syncthreads();

    // ---- Phase 2: fused vertical 5-sums + deviations + product (registers) ----
    const int q     = tid % MID_W;          // column 0..131
    const int strip = tid / MID_W;          // 0 or 1 (strip*26 rows)
    const bool act  = tid < 2 * MID_W;      // 264 workers
    const int p0    = strip * (MID_H / 2);  // 0 or 26

    float pr[MID_H / 2];                    // 26 product values in registers

    if (act) {
        const float* cA = hA + q;
        const float* cB = hB + q;
        float sA = cA[(p0  )*HS] + cA[(p0+1)*HS] + cA[(p0+2)*HS]
                 + cA[(p0+3)*HS] + cA[(p0+4)*HS];
        float sB = cB[(p0  )*HS] + cB[(p0+1)*HS] + cB[(p0+2)*HS]
                 + cB[(p0+3)*HS] + cB[(p0+4)*HS];

        const int  gc   = bx + q + 2;
        const bool gcok = (gc < IMG);
        const float* xc = xp + (size_t)(by + p0 + 2) * IMG + gc;
        const float* yc = yp + (size_t)(by + p0 + 2) * IMG + gc;

        #pragma unroll
        for (int k = 0; k < MID_H / 2; ++k) {
            const int p  = p0 + k;
            const int gr = by + p + 2;
            const bool ok = gcok && (gr < IMG);
            float xv = ok ? xc[(size_t)k * IMG] : 0.f;   // L2-hit re-read of center
            float yv = ok ? yc[(size_t)k * IMG] : 0.f;
            float dA = xv - sA * 0.04f;
            float dB = yv - sB * 0.04f;
            pr[k] = dA * dB;
            if (k < MID_H / 2 - 1) {
                sA += cA[(p + 5) * HS] - cA[p * HS];
                sB += cB[(p + 5) * HS] - cB[p * HS];
            }
        }
    }
    __syncthreads();               // all reads of hA/hB complete

    if (act) {                     // prod overlays hA region: [MID_H][HS]
        float* pc = hA + q;
        #pragma unroll
        for (int k = 0; k < MID_H / 2; ++k)
            pc[(p0 + k) * HS] = pr[k];
    }
    __syncthreads();

    // ---- Phase 3: horizontal 5-sum of product (shuffle, cols 0..127 only) ----
    for (int p = wid; p < MID_H; p += NW) {
        const float* row = hA + p * HS;
        float4 v  = *(const float4*)(row + 4 * ln);
        float4 v2 = (ln == 0) ? *(const float4*)(row + 128) : z4;
        hrow_sum(v, v2, hB + p * HS, ln, false);   // hprod overlays hB
    }
    __syncthreads();

    // ---- Phase 4: vertical 5-sum * 1/25 -> global store ----
    if (tid < 256) {
        const int j  = tid & 127;
        const int s2 = tid >> 7;               // strip 0/1
        const int i0 = s2 * (TILE_H / 2);      // 0 or 24
        const int ox = bx + j;
        const float* hc = hB + j;
        float m = hc[(i0  )*HS] + hc[(i0+1)*HS] + hc[(i0+2)*HS]
                + hc[(i0+3)*HS] + hc[(i0+4)*HS];
        float* ob = out + (size_t)n * OUTD * OUTD;
        #pragma unroll
        for (int k = 0; k < TILE_H / 2; ++k) {
            const int i  = i0 + k;
            const int oy = by + i;
            if (ox < OUTD && oy < OUTD)
                ob[(size_t)oy * OUTD + ox] = m * 0.04f;
            if (k < TILE_H / 2 - 1)
                m += hc[(i + 5) * HS] - hc[i * HS];
        }
    }
}

extern "C" void kernel_launch(void* const* d_in, const int* in_sizes, int n_in,
                              void* d_out, int out_size) {
    const float* x = (const float*)d_in[0];
    const float* y = (const float*)d_in[1];
    // d_in[2] = mean_mask (uniform 1/25, folded into the 0.04f constants)
    float* out = (float*)d_out;

    const int smem = 2 * IN_H * HS * (int)sizeof(float);   // 60928 B
    cudaFuncSetAttribute(cov_kernel, cudaFuncAttributeMaxDynamicSharedMemorySize, smem);

    dim3 grid((OUTD + TILE_W - 1) / TILE_W,    // 8
              (OUTD + TILE_H - 1) / TILE_H,    // 22
              16);
    cov_kernel<<<grid, NT, smem>>>(x, y, out);
}